// round 12
// baseline (speedup 1.0000x reference)
#include <cuda_runtime.h>

typedef unsigned long long ull;

#define T_ 32
#define H_ 56
#define W_ 56
#define HW 3136
#define C_ 64
#define B_ 4
#define TILEH 8
#define NTILES 7
#define NT 224            // 28 pixel-pairs * 8 rows
#define WDY 28            // ull stride per dy in packed weight array

#define MODP(x, m) ((((x) + 24) % (m)))   // +24 divisible by 3,4,6,8

#define FMA2(acc, w, x) \
    asm("fma.rn.f32x2 %0, %1, %2, %0;" : "+l"(acc) : "l"(w), "l"(x))
#define MUL2(acc, w, x) \
    asm("mul.rn.f32x2 %0, %1, %2;" : "=l"(acc) : "l"(w), "l"(x))
#define UNPK(lo, hi, p) \
    asm("mov.b64 {%0,%1}, %2;" : "=f"(lo), "=f"(hi) : "l"(p))
#define PACK2(p, lo, hi) \
    asm("mov.b64 %0, {%1,%2};" : "=l"(p) : "f"(lo), "f"(hi))

__device__ __forceinline__ float sgm(float v) {
    return __fdividef(1.0f, 1.0f + __expf(-v)) - 0.5f;
}

__global__ void __launch_bounds__(NT, 3) tts_kernel(
    const float* __restrict__ xg,
    const float* __restrict__ w1g, const float* __restrict__ b1g,
    const float* __restrict__ w2g, const float* __restrict__ b2g,
    const float* __restrict__ w3g, const float* __restrict__ b3g,
    const float* __restrict__ wgg,
    float* __restrict__ outg)
{
    // No plane staging, no cp.async, no per-round barriers: warps run
    // autonomously after one init barrier. Input read directly from global;
    // the 3x dy re-read is absorbed by L1 (per-SM working set ~20KB).
    __shared__ __align__(16) ull wpk[3][WDY];      // [dy][sl*3+k] dup'd taps
    __shared__ __align__(16) float2 hsm[5][NT];    // 0..1 = h2, 2..4 = h3

    const int tid  = threadIdx.x;
    const int bx   = blockIdx.x;
    const int tile = bx % NTILES;
    const int bc   = bx / NTILES;      // b*C + c
    const int c    = bc % C_;
    const int h0   = tile * TILEH;

    const float* __restrict__ xin = xg + (size_t)bc * (T_ * HW);
    float* __restrict__ op = outg + (size_t)bc * (T_ * HW);

    // Stage packed duplicated weights: wpk[dy][sl*3+k] = (w,w), tap dy*3+k
    if (tid < 108) {
        int k = tid & 3, rowi = tid >> 2;       // 27 (sl,dy) rows
        int sl = rowi / 3, dy = rowi % 3;
        int i = sl / 3, s = sl % 3;
        if (k < 3) {
            const float* wp = (i == 0) ? w1g : (i == 1) ? w2g : w3g;
            unsigned b = __float_as_uint(wp[c * 27 + s * 9 + dy * 3 + k]);
            wpk[dy][sl * 3 + k] = ((ull)b << 32) | b;
        }
    }

    const float bias0 = b1g[c], bias1 = b2g[c], bias2 = b3g[c];
    const float wt0 = wgg[0], wt1 = wgg[1], wt2 = wgg[2];

    const int row = tid / 28;          // 0..7
    const int wpi = tid % 28;          // pair index
    const int w0  = wpi * 2;           // 0..54

    // One base pointer; every load in the unrolled kernel is base + imm.
    // colp points at (dy=0 row, x=w0): plane t, dy -> colp + t*HW + dy*W.
    const float* colp = xin + (h0 + row - 1) * W_ + w0;
    float* outp = op + (h0 + row) * W_ + w0;

    const bool leftOK  = (wpi > 0);
    const bool rightOK = (wpi < 27);
    const bool topOK   = !(tile == 0 && row == 0);
    const bool botOK   = !(tile == NTILES - 1 && row == TILEH - 1);

    // Zero h2/h3 histories (same-thread access only afterwards)
    #pragma unroll
    for (int j = 0; j < 5; ++j) hsm[j][tid] = make_float2(0.f, 0.f);
    __syncthreads();   // the only block barrier (weights + hsm visible)

    // Accumulator rings (packed f32x2), pair-round sizes 2d+2 = 4/6/8.
    // Zero-init covers targets t<d; all other slot uses begin with MUL2
    // overwrite from slice s=0 (garbage from t<0 aliases is provably
    // overwritten one round later, before any read).
    ull R1[4], R2[6], R3[8];
    #pragma unroll
    for (int j = 0; j < 4; ++j) R1[j] = 0ull;
    #pragma unroll
    for (int j = 0; j < 6; ++j) R2[j] = 0ull;
    #pragma unroll
    for (int j = 0; j < 8; ++j) R3[j] = 0ull;

    // Gate ring + conv1 history in registers (conv1 overwrites G first).
    float Gx[3], Gy[3];
    float2 h1 = make_float2(0.f, 0.f);
    #pragma unroll
    for (int j = 0; j < 3; ++j) { Gx[j] = 0.f; Gy[j] = 0.f; }

    // ring target for slice sl applied at plane p: t = p + (1-s)*d
    auto aref = [&](int sl, int p) -> ull& {
        int cv = sl / 3, s = sl % 3;
        if (cv == 0) return R1[MODP(p + (1 - s) * 1, 4)];
        if (cv == 1) return R2[MODP(p + (1 - s) * 2, 6)];
        return R3[MODP(p + (1 - s) * 3, 8)];
    };

    auto tap3 = [&](int sl, int p, bool fresh,
                    ull w0v, ull w1v, ull w2v,
                    ull a01, ull am, ull a23) {
        ull& q_ = aref(sl, p);
        if (fresh) { MUL2(q_, w0v, a01); }
        else       { FMA2(q_, w0v, a01); }
        FMA2(q_, w1v, am);
        FMA2(q_, w2v, a23);
    };

    auto completion = [&](int tau) {
        // conv1: y1(tau-1). First gate writer -> overwrite G (regs).
        if (tau >= 1 && tau <= T_) {
            float lo, hi; UNPK(lo, hi, R1[MODP(tau - 1, 4)]);
            float y0 = lo + bias0, y1 = hi + bias0;
            float d0 = y0, d1 = y1;
            if (tau >= 2) { d0 -= h1.x; d1 -= h1.y; }
            h1 = make_float2(y0, y1);
            const int gs = MODP(tau - 1, 3);
            Gx[gs] = sgm(d0) * wt0;
            Gy[gs] = sgm(d1) * wt0;
        }

        // conv2: y2(tau-2), gate RMW
        if (tau >= 2 && tau <= T_ + 1) {
            float lo, hi; UNPK(lo, hi, R2[MODP(tau - 2, 6)]);
            float y0 = lo + bias1, y1 = hi + bias1;
            float d0 = y0, d1 = y1;
            const int hs = tau % 2;             // (tau-2)%2
            if (tau >= 4) {
                float2 h = hsm[hs][tid];
                d0 -= h.x; d1 -= h.y;
            }
            hsm[hs][tid] = make_float2(y0, y1);
            const int gs = MODP(tau - 2, 3);
            Gx[gs] += sgm(d0) * wt1;
            Gy[gs] += sgm(d1) * wt1;
        }

        // conv3: y3(tau-3) -> gate complete -> output t = tau-3
        if (tau >= 3 && tau <= T_ + 2) {
            float lo, hi; UNPK(lo, hi, R3[MODP(tau - 3, 8)]);
            float y0 = lo + bias2, y1 = hi + bias2;
            float d0 = y0, d1 = y1;
            const int hs = 2 + (tau % 3);       // (tau-3)%3
            if (tau >= 6) {
                float2 h = hsm[hs][tid];
                d0 -= h.x; d1 -= h.y;
            }
            hsm[hs][tid] = make_float2(y0, y1);
            const int gs = MODP(tau - 3, 3);
            float g0 = Gx[gs] + sgm(d0) * wt2;
            float g1 = Gy[gs] + sgm(d1) * wt2;

            const int tout = tau - 3;
            // center pair: dy=1 row of plane tout (L1-resident)
            float2 cx = *(const float2*)(colp + (size_t)tout * HW + W_);
            float2 o = make_float2(cx.x * g0, cx.y * g1);
            *(float2*)(outp + (size_t)tout * HW) = o;
        }
    };

    #pragma unroll
    for (int q = 0; q < 18; ++q) {
        const int tA = 2 * q, tB = 2 * q + 1;

        if (tA < T_) {
            #pragma unroll
            for (int dy = 0; dy < 3; ++dy) {
                const bool rok = (dy == 0) ? topOK : ((dy == 2) ? botOK : true);
                ull a01[2], am[2], a23[2];
                #pragma unroll
                for (int jj = 0; jj < 2; ++jj) {
                    const float* rp = colp + (size_t)(tA + jj) * HW + dy * W_;
                    ull m = rok ? *(const ull*)rp : 0ull;
                    float lf = (rok && leftOK)  ? rp[-1] : 0.f;
                    float rt = (rok && rightOK) ? rp[2]  : 0.f;
                    float mx, my; UNPK(mx, my, m);
                    am[jj] = m;
                    PACK2(a01[jj], lf, mx);
                    PACK2(a23[jj], my, rt);
                }

                const ull* wrow = &wpk[dy][0];
                // 4 slice-pairs: 3 aligned 16B loads cover 2 slices' 6 taps
                #pragma unroll
                for (int pr = 0; pr < 4; ++pr) {
                    const int slA = 2 * pr, slB = 2 * pr + 1;
                    ulonglong2 q0 = *(const ulonglong2*)(wrow + 6 * pr);
                    ulonglong2 q1 = *(const ulonglong2*)(wrow + 6 * pr + 2);
                    ulonglong2 q2 = *(const ulonglong2*)(wrow + 6 * pr + 4);
                    const bool f0 = (slA % 3) == 0 && dy == 0;
                    const bool f1 = (slB % 3) == 0 && dy == 0;
                    #pragma unroll
                    for (int jj = 0; jj < 2; ++jj) {
                        tap3(slA, tA + jj, f0, q0.x, q0.y, q1.x,
                             a01[jj], am[jj], a23[jj]);
                        tap3(slB, tA + jj, f1, q1.y, q2.x, q2.y,
                             a01[jj], am[jj], a23[jj]);
                    }
                }
                {   // slice 8 (conv3, s=2)
                    ulonglong2 q0 = *(const ulonglong2*)(wrow + 24);
                    ull w2v = wrow[26];
                    #pragma unroll
                    for (int jj = 0; jj < 2; ++jj)
                        tap3(8, tA + jj, false, q0.x, q0.y, w2v,
                             a01[jj], am[jj], a23[jj]);
                }
            }
        }

        completion(tA);
        if (tB <= T_ + 2) completion(tB);
    }
}

extern "C" void kernel_launch(void* const* d_in, const int* in_sizes, int n_in,
                              void* d_out, int out_size) {
    const float* x  = (const float*)d_in[0];
    const float* w1 = (const float*)d_in[1];
    const float* b1 = (const float*)d_in[2];
    const float* w2 = (const float*)d_in[3];
    const float* b2 = (const float*)d_in[4];
    const float* w3 = (const float*)d_in[5];
    const float* b3 = (const float*)d_in[6];
    const float* wg = (const float*)d_in[7];
    float* out = (float*)d_out;

    dim3 grid(B_ * C_ * NTILES);   // 1792
    dim3 block(NT);                // 224
    tts_kernel<<<grid, block>>>(x, w1, b1, w2, b2, w3, b3, wg, out);
}

// round 16
// speedup vs baseline: 1.8772x; 1.8772x over previous
#include <cuda_runtime.h>

typedef unsigned long long ull;

#define T_ 32
#define H_ 56
#define W_ 56
#define HW 3136
#define C_ 64
#define B_ 4
#define TILEH 8
#define NTILES 7
#define NT 256            // 8 warps; warp w owns tile row w (28 pairs, lanes 0..27)
#define NW 8
#define SLOTS 7           // per-warp plane ring
#define RBUF 72           // floats per staged row: cols 0..63 written (col = x+4), 8 pad
#define SLOTF (3 * RBUF)  // 216 floats per slot
#define WDY 28            // ull stride per dy in packed weights

#define PBUF_BYTES (NW * SLOTS * SLOTF * 4)      // 48384
#define WPK_OFF    PBUF_BYTES                    // 48384 (16B aligned)
#define HSM_OFF    (WPK_OFF + 3 * WDY * 8)       // 49056 (16B aligned)
#define SMEM_TOTAL (HSM_OFF + 5 * NT * 8)        // 59296

#define MODP(x, m) ((((x) + 168) % (m)))  // 168 divisible by 3,4,6,7,8

#define FMA2(acc, w, x) \
    asm("fma.rn.f32x2 %0, %1, %2, %0;" : "+l"(acc) : "l"(w), "l"(x))
#define MUL2(acc, w, x) \
    asm("mul.rn.f32x2 %0, %1, %2;" : "=l"(acc) : "l"(w), "l"(x))
#define UNPK(lo, hi, p) \
    asm("mov.b64 {%0,%1}, %2;" : "=f"(lo), "=f"(hi) : "l"(p))
#define MIDP(m, p01, p23) \
    asm("{ .reg .b32 t0,t1,t2,t3;\n\t mov.b64 {t0,t1}, %1;\n\t" \
        " mov.b64 {t2,t3}, %2;\n\t mov.b64 %0, {t1,t2}; }" \
        : "=l"(m) : "l"(p01), "l"(p23))
#define CPA16(saddr, gaddr, sz) \
    asm volatile("cp.async.ca.shared.global [%0], [%1], 16, %2;" \
                 :: "r"(saddr), "l"(gaddr), "r"(sz) : "memory")
#define CP_COMMIT asm volatile("cp.async.commit_group;" ::: "memory")
#define CP_WAIT1  asm volatile("cp.async.wait_group 1;" ::: "memory")

__device__ __forceinline__ float sgm(float v) {
    return __fdividef(1.0f, 1.0f + __expf(-v)) - 0.5f;
}

extern __shared__ __align__(16) char smem_[];

__global__ void __launch_bounds__(NT, 3) tts_kernel(
    const float* __restrict__ xg,
    const float* __restrict__ w1g, const float* __restrict__ b1g,
    const float* __restrict__ w2g, const float* __restrict__ b2g,
    const float* __restrict__ w3g, const float* __restrict__ b3g,
    const float* __restrict__ wgg,
    float* __restrict__ outg)
{
    float* const pbufF = (float*)smem_;
    ull*   const wpk   = (ull*)(smem_ + WPK_OFF);     // [dy*WDY + sl*3+k]
    float2* const hsm  = (float2*)(smem_ + HSM_OFF);  // [j*NT + tid], j 0..4

    const int tid  = threadIdx.x;
    const int lane = tid & 31;
    const int w    = tid >> 5;         // warp id = tile row
    const int bx   = blockIdx.x;
    const int tile = bx % NTILES;
    const int bc   = bx / NTILES;
    const int c    = bc % C_;
    const int h0   = tile * TILEH;

    const float* __restrict__ xin = xg + (size_t)bc * (T_ * HW);
    float* __restrict__ op = outg + (size_t)bc * (T_ * HW);

    // Packed duplicated weights: wpk[dy*WDY + sl*3+k] = (w,w) for tap dy*3+k
    if (tid < 108) {
        int k = tid & 3, rowi = tid >> 2;
        int sl = rowi / 3, dy = rowi % 3;
        int i = sl / 3, s = sl % 3;
        if (k < 3) {
            const float* wp = (i == 0) ? w1g : (i == 1) ? w2g : w3g;
            unsigned b = __float_as_uint(wp[c * 27 + s * 9 + dy * 3 + k]);
            wpk[dy * WDY + sl * 3 + k] = ((ull)b << 32) | b;
        }
    }

    const float bias0 = b1g[c], bias1 = b2g[c], bias2 = b3g[c];
    const float wt0 = wgg[0], wt1 = wgg[1], wt2 = wgg[2];

    // Per-warp staging tasks: 48 16B chunks (3 rows x 16) per plane.
    // Chunk k of row rr covers buffer cols 4k..4k+3 = x in [4k-4, 4k-1].
    // Fully-OOB chunks (k=0, k=15, OOB rows) are zero-filled via src-size 0.
    const int rr0 = lane >> 4, k0 = lane & 15;
    const int y0a = h0 + w - 1 + rr0;
    const bool in0 = (k0 >= 1) && (k0 <= 14) && (y0a >= 0) && (y0a < H_);
    const unsigned sb0 = (unsigned)((rr0 * RBUF + k0 * 4) * 4);
    const int gb0 = in0 ? ((y0a * W_ + k0 * 4 - 4) * 4) : 0;
    const int sz0 = in0 ? 16 : 0;
    const bool act1 = (lane < 16);
    const int y1a = h0 + w + 1;
    const bool in1 = act1 && (lane >= 1) && (lane <= 14) && (y1a < H_);
    const unsigned sb1 = (unsigned)((2 * RBUF + lane * 4) * 4);
    const int gb1 = in1 ? ((y1a * W_ + lane * 4 - 4) * 4) : 0;
    const int sz1 = in1 ? 16 : 0;

    const unsigned pb = (unsigned)__cvta_generic_to_shared(pbufF);
    const int wslot = w * SLOTS;
    const char* const xb = (const char*)xin;

    auto stage = [&](int p) {   // warp-private; p literal after unroll
        unsigned sbase = pb + (unsigned)((wslot + MODP(p, SLOTS)) * (SLOTF * 4));
        const char* g = xb + (size_t)p * (HW * 4);
        CPA16(sbase + sb0, g + gb0, sz0);
        if (act1) CPA16(sbase + sb1, g + gb1, sz1);
    };

    // Zero h2/h3 histories (own-slot access only afterwards)
    #pragma unroll
    for (int j = 0; j < 5; ++j) hsm[j * NT + tid] = make_float2(0.f, 0.f);
    __syncthreads();   // the only block barrier (weights + hsm visible)

    const bool act = (lane < 28);          // conv/output lanes
    float* const outp = op + (h0 + w) * W_ + 2 * lane;

    // Accumulator rings (packed f32x2), pair-round sizes 4/6/8.
    // Zero-init covers t<d; all other uses start with MUL2 overwrite (s=0).
    ull R1[4], R2[6], R3[8];
    #pragma unroll
    for (int j = 0; j < 4; ++j) R1[j] = 0ull;
    #pragma unroll
    for (int j = 0; j < 6; ++j) R2[j] = 0ull;
    #pragma unroll
    for (int j = 0; j < 8; ++j) R3[j] = 0ull;

    float Gx[3], Gy[3];
    float2 h1 = make_float2(0.f, 0.f);
    #pragma unroll
    for (int j = 0; j < 3; ++j) { Gx[j] = 0.f; Gy[j] = 0.f; }

    auto aref = [&](int sl, int p) -> ull& {
        int cv = sl / 3, s = sl % 3;
        if (cv == 0) return R1[MODP(p + (1 - s) * 1, 4)];
        if (cv == 1) return R2[MODP(p + (1 - s) * 2, 6)];
        return R3[MODP(p + (1 - s) * 3, 8)];
    };

    auto tap3 = [&](int sl, int p, bool fresh,
                    ull w0v, ull w1v, ull w2v,
                    ull a01, ull am, ull a23) {
        ull& q_ = aref(sl, p);
        if (fresh) { MUL2(q_, w0v, a01); }
        else       { FMA2(q_, w0v, a01); }
        FMA2(q_, w1v, am);
        FMA2(q_, w2v, a23);
    };

    auto completion = [&](int tau) {
        // conv1: y1(tau-1), first gate writer (overwrite G in regs)
        if (tau >= 1 && tau <= T_) {
            float lo, hi; UNPK(lo, hi, R1[MODP(tau - 1, 4)]);
            float y0 = lo + bias0, y1 = hi + bias0;
            float d0 = y0, d1 = y1;
            if (tau >= 2) { d0 -= h1.x; d1 -= h1.y; }
            h1 = make_float2(y0, y1);
            const int gs = MODP(tau - 1, 3);
            Gx[gs] = sgm(d0) * wt0;
            Gy[gs] = sgm(d1) * wt0;
        }

        // conv2: y2(tau-2), gate RMW
        if (tau >= 2 && tau <= T_ + 1) {
            float lo, hi; UNPK(lo, hi, R2[MODP(tau - 2, 6)]);
            float y0 = lo + bias1, y1 = hi + bias1;
            float d0 = y0, d1 = y1;
            const int hs = tau % 2;
            if (tau >= 4) {
                float2 h = hsm[hs * NT + tid];
                d0 -= h.x; d1 -= h.y;
            }
            hsm[hs * NT + tid] = make_float2(y0, y1);
            const int gs = MODP(tau - 2, 3);
            Gx[gs] += sgm(d0) * wt1;
            Gy[gs] += sgm(d1) * wt1;
        }

        // conv3: y3(tau-3) -> gate complete -> output t = tau-3
        if (tau >= 3 && tau <= T_ + 2) {
            float lo, hi; UNPK(lo, hi, R3[MODP(tau - 3, 8)]);
            float y0 = lo + bias2, y1 = hi + bias2;
            float d0 = y0, d1 = y1;
            const int hs = 2 + (tau % 3);
            if (tau >= 6) {
                float2 h = hsm[hs * NT + tid];
                d0 -= h.x; d1 -= h.y;
            }
            hsm[hs * NT + tid] = make_float2(y0, y1);
            const int gs = MODP(tau - 3, 3);
            float g0 = Gx[gs] + sgm(d0) * wt2;
            float g1 = Gy[gs] + sgm(d1) * wt2;

            const int tout = tau - 3;
            // center pair: dy=1 row of plane tout, cols (2l+4, 2l+5)
            const float* cp = pbufF + (wslot + MODP(tout, SLOTS)) * SLOTF
                              + RBUF + 2 * lane + 4;
            float2 cx = *(const float2*)cp;
            if (act) {
                float2 o = make_float2(cx.x * g0, cx.y * g1);
                *(float2*)(outp + (size_t)tout * HW) = o;
            }
        }
    };

    // Prologue: stage planes 0,1 as one group
    stage(0); stage(1); CP_COMMIT;

    #pragma unroll
    for (int q = 0; q < 18; ++q) {
        const int tA = 2 * q, tB = 2 * q + 1;

        if (tA < T_) {
            if (tA + 2 < T_) stage(tA + 2);
            if (tA + 3 < T_) stage(tA + 3);
            CP_COMMIT;
            CP_WAIT1;              // previous pair resident (warp-private)
            __syncwarp();

            #pragma unroll
            for (int dy = 0; dy < 3; ++dy) {
                ull a01[2], am[2], a23[2];
                #pragma unroll
                for (int jj = 0; jj < 2; ++jj) {
                    const float* rw = pbufF
                        + (wslot + MODP(tA + jj, SLOTS)) * SLOTF
                        + dy * RBUF + 2 * lane;
                    ull prev = *(const ull*)(rw + 2);
                    ull m    = *(const ull*)(rw + 4);
                    ull nxt  = *(const ull*)(rw + 6);
                    MIDP(a01[jj], prev, m);
                    am[jj] = m;
                    MIDP(a23[jj], m, nxt);
                }

                const ull* wrow = wpk + dy * WDY;
                #pragma unroll
                for (int pr = 0; pr < 4; ++pr) {
                    const int slA = 2 * pr, slB = 2 * pr + 1;
                    ulonglong2 q0 = *(const ulonglong2*)(wrow + 6 * pr);
                    ulonglong2 q1 = *(const ulonglong2*)(wrow + 6 * pr + 2);
                    ulonglong2 q2 = *(const ulonglong2*)(wrow + 6 * pr + 4);
                    const bool f0 = (slA % 3) == 0 && dy == 0;
                    const bool f1 = (slB % 3) == 0 && dy == 0;
                    #pragma unroll
                    for (int jj = 0; jj < 2; ++jj) {
                        tap3(slA, tA + jj, f0, q0.x, q0.y, q1.x,
                             a01[jj], am[jj], a23[jj]);
                        tap3(slB, tA + jj, f1, q1.y, q2.x, q2.y,
                             a01[jj], am[jj], a23[jj]);
                    }
                }
                {   // slice 8 (conv3, s=2)
                    ulonglong2 q0 = *(const ulonglong2*)(wrow + 24);
                    ull w2v = wrow[26];
                    #pragma unroll
                    for (int jj = 0; jj < 2; ++jj)
                        tap3(8, tA + jj, false, q0.x, q0.y, w2v,
                             a01[jj], am[jj], a23[jj]);
                }
            }
        }

        completion(tA);
        if (tB <= T_ + 2) completion(tB);
    }
}

extern "C" void kernel_launch(void* const* d_in, const int* in_sizes, int n_in,
                              void* d_out, int out_size) {
    const float* x  = (const float*)d_in[0];
    const float* w1 = (const float*)d_in[1];
    const float* b1 = (const float*)d_in[2];
    const float* w2 = (const float*)d_in[3];
    const float* b2 = (const float*)d_in[4];
    const float* w3 = (const float*)d_in[5];
    const float* b3 = (const float*)d_in[6];
    const float* wg = (const float*)d_in[7];
    float* out = (float*)d_out;

    // Dynamic smem (59.3 KB > 48 KB static limit) + max carveout.
    // Host-side attributes, set outside graph capture, deterministic.
    static int attrs_set = 0;
    if (!attrs_set) {
        cudaFuncSetAttribute(tts_kernel,
                             cudaFuncAttributeMaxDynamicSharedMemorySize,
                             SMEM_TOTAL);
        cudaFuncSetAttribute(tts_kernel,
                             cudaFuncAttributePreferredSharedMemoryCarveout,
                             100);
        attrs_set = 1;
    }

    dim3 grid(B_ * C_ * NTILES);   // 1792
    dim3 block(NT);                // 256 (8 warps)
    tts_kernel<<<grid, block, SMEM_TOTAL>>>(x, w1, b1, w2, b2, w3, b3, wg, out);
}

// round 17
// speedup vs baseline: 1.9150x; 1.0201x over previous
#include <cuda_runtime.h>

typedef unsigned long long ull;

#define T_ 32
#define H_ 56
#define W_ 56
#define HW 3136
#define C_ 64
#define B_ 4
#define TILEH 8
#define NTILES 7
#define NT 224            // 28 pixel-pairs * 8 rows
#define RS 60             // padded row stride (floats)
#define PR (TILEH + 2)
#define SLOTS 12          // stage{+3..+5} vs reads{-6..+2}: diffs 1..11, !=0 mod 12
#define PLANEF (PR * RS)  // 600

#define MODP(x, m) ((((x) + 1260) % (m)))   // 1260 divisible by 3,5,7,9,12

#define FMA2(acc, w, x) \
    asm("fma.rn.f32x2 %0, %1, %2, %0;" : "+l"(acc) : "l"(w), "l"(x))
#define MUL2(acc, w, x) \
    asm("mul.rn.f32x2 %0, %1, %2;" : "=l"(acc) : "l"(w), "l"(x))
#define UNPK(lo, hi, p) \
    asm("mov.b64 {%0,%1}, %2;" : "=f"(lo), "=f"(hi) : "l"(p))
#define MIDP(m, p01, p23) \
    asm("{ .reg .b32 t0,t1,t2,t3;\n\t mov.b64 {t0,t1}, %1;\n\t" \
        " mov.b64 {t2,t3}, %2;\n\t mov.b64 %0, {t1,t2}; }" \
        : "=l"(m) : "l"(p01), "l"(p23))
#define CPA(saddr, gaddr, sz) \
    asm volatile("cp.async.ca.shared.global [%0], [%1], 4, %2;" \
                 :: "r"(saddr), "l"(gaddr), "r"(sz) : "memory")
#define CP_COMMIT asm volatile("cp.async.commit_group;" ::: "memory")
#define CP_WAIT1  asm volatile("cp.async.wait_group 1;" ::: "memory")

// sigmoid(v) = rcp(1 + 2^(-v*log2e)); approx MUFU ops, err ~2e-7 << 1e-3
__device__ __forceinline__ float sigr(float v) {
    float e, r;
    asm("ex2.approx.f32 %0, %1;" : "=f"(e) : "f"(v * -1.44269504f));
    asm("rcp.approx.f32 %0, %1;" : "=f"(r) : "f"(1.0f + e));
    return r;
}

__global__ void __launch_bounds__(NT, 3) tts_kernel(
    const float* __restrict__ xg,
    const float* __restrict__ w1g, const float* __restrict__ b1g,
    const float* __restrict__ w2g, const float* __restrict__ b2g,
    const float* __restrict__ w3g, const float* __restrict__ b3g,
    const float* __restrict__ wgg,
    float* __restrict__ outg)
{
    __shared__ __align__(16) float plane[SLOTS][PR][RS];     // 28800 B
    __shared__ __align__(16) ull wdup[9][3][4];              // dup'd weights
    __shared__ __align__(16) float2 hsm[6][NT];              // 0=h1,1..2=h2,3..5=h3
    __shared__ __align__(16) float2 gbuf[3][NT];             // gate ring

    const int tid  = threadIdx.x;
    const int bx   = blockIdx.x;
    const int tile = bx % NTILES;
    const int bc   = bx / NTILES;
    const int c    = bc % C_;
    const int h0   = tile * TILEH;

    const float* __restrict__ xin = xg + (size_t)bc * (T_ * HW);
    float* __restrict__ op = outg + (size_t)bc * (T_ * HW);

    // Stage duplicated weights: wdup[sl][dy][j] = (w,w) for tap dy*3+j
    if (tid < 108) {
        int j = tid & 3, rowi = tid >> 2;
        int sl = rowi / 3, dy = rowi % 3;
        int i = sl / 3, s = sl % 3;
        ull v = 0;
        if (j < 3) {
            const float* wp = (i == 0) ? w1g : (i == 1) ? w2g : w3g;
            unsigned b = __float_as_uint(wp[c * 27 + s * 9 + dy * 3 + j]);
            v = ((ull)b << 32) | b;
        }
        wdup[sl][dy][j] = v;
    }

    const float bias0 = b1g[c], bias1 = b2g[c], bias2 = b3g[c];
    const float wt0 = wgg[0], wt1 = wgg[1], wt2 = wgg[2];
    const float Kc = 0.5f * (wt0 + wt1 + wt2);   // folded -0.5 terms

    // Staging geometry: 600 floats/plane, 3 elems/thread (k=2 partial)
    unsigned sb[3]; const char* gb[3]; int sz[3];
    #pragma unroll
    for (int k = 0; k < 3; ++k) {
        int idx = tid + k * NT;
        bool a = (idx < PLANEF);
        int r = idx / RS, col = idx % RS;
        int y = h0 - 1 + r, xw = col - 1;
        bool in = a && (y >= 0) && (y < H_) && (xw >= 0) && (xw < W_);
        sb[k] = (unsigned)((r * RS + col) * 4);
        gb[k] = (const char*)(xin + (in ? (y * W_ + xw) : 0));
        sz[k] = in ? 4 : 0;
    }
    const bool act2 = (tid + 2 * NT) < PLANEF;
    const unsigned pbase = (unsigned)__cvta_generic_to_shared(&plane[0][0][0]);
    const float* const plane0 = &plane[0][0][0];

    auto stage = [&](int p) {   // p compile-time literal after unroll
        unsigned sdst = pbase + (unsigned)(MODP(p, SLOTS) * PLANEF * 4);
        size_t go = (size_t)p * (HW * 4);
        CPA(sdst + sb[0], gb[0] + go, sz[0]);
        CPA(sdst + sb[1], gb[1] + go, sz[1]);
        if (act2) CPA(sdst + sb[2], gb[2] + go, sz[2]);
    };

    // Zero histories + gate ring (same-thread access only)
    #pragma unroll
    for (int j = 0; j < 6; ++j) hsm[j][tid] = make_float2(0.f, 0.f);
    #pragma unroll
    for (int j = 0; j < 3; ++j) gbuf[j][tid] = make_float2(0.f, 0.f);

    const int nb0   = (tid / 28) * RS + (tid % 28) * 2;
    const int obase = (h0 + tid / 28) * W_ + (tid % 28) * 2;

    // Accumulator rings (packed f32x2). Zero-init covers targets t < d;
    // all other slot uses begin with MUL2 from slice s=0 (no resets).
    ull R1[5], R2[7], R3[9];
    #pragma unroll
    for (int j = 0; j < 5; ++j) R1[j] = 0ull;
    #pragma unroll
    for (int j = 0; j < 7; ++j) R2[j] = 0ull;
    #pragma unroll
    for (int j = 0; j < 9; ++j) R3[j] = 0ull;

    // ring target for slice sl applied at plane p: t = p + (1-s)*d
    auto aref = [&](int sl, int t) -> ull& {
        int cv = sl / 3, s = sl % 3;
        if (cv == 0) return R1[MODP(t + (1 - s) * 1, 5)];
        if (cv == 1) return R2[MODP(t + (1 - s) * 2, 7)];
        return R3[MODP(t + (1 - s) * 3, 9)];
    };

    auto completion = [&](int tau) {
        // conv1: y1(tau-1). First gate writer -> overwrite gbuf, K folded in.
        if (tau >= 1 && tau <= T_) {
            float lo, hi; UNPK(lo, hi, R1[MODP(tau - 1, 5)]);
            float y0 = lo + bias0, y1 = hi + bias0;
            float d0 = y0, d1 = y1;
            if (tau >= 2) {
                float2 h = hsm[0][tid];
                d0 -= h.x; d1 -= h.y;
            }
            hsm[0][tid] = make_float2(y0, y1);
            gbuf[MODP(tau - 1, 3)][tid] =
                make_float2(fmaf(sigr(d0), wt0, -Kc),
                            fmaf(sigr(d1), wt0, -Kc));
        }

        // conv2: y2(tau-2), gate RMW
        if (tau >= 2 && tau <= T_ + 1) {
            float lo, hi; UNPK(lo, hi, R2[MODP(tau - 2, 7)]);
            float y0 = lo + bias1, y1 = hi + bias1;
            float d0 = y0, d1 = y1;
            const int hs = 1 + (tau % 2);       // (tau-2)%2
            if (tau >= 4) {
                float2 h = hsm[hs][tid];
                d0 -= h.x; d1 -= h.y;
            }
            hsm[hs][tid] = make_float2(y0, y1);
            float2 g = gbuf[MODP(tau - 2, 3)][tid];
            g.x = fmaf(sigr(d0), wt1, g.x);
            g.y = fmaf(sigr(d1), wt1, g.y);
            gbuf[MODP(tau - 2, 3)][tid] = g;
        }

        // conv3: y3(tau-3) -> gate complete -> output t = tau-3
        if (tau >= 3 && tau <= T_ + 2) {
            float lo, hi; UNPK(lo, hi, R3[MODP(tau - 3, 9)]);
            float y0 = lo + bias2, y1 = hi + bias2;
            float d0 = y0, d1 = y1;
            const int hs = 3 + (tau % 3);       // (tau-3)%3
            if (tau >= 6) {
                float2 h = hsm[hs][tid];
                d0 -= h.x; d1 -= h.y;
            }
            hsm[hs][tid] = make_float2(y0, y1);
            float2 g = gbuf[MODP(tau - 3, 3)][tid];
            float g0 = fmaf(sigr(d0), wt2, g.x);
            float g1 = fmaf(sigr(d1), wt2, g.y);

            const int tout = tau - 3;
            const float* pc = plane0 + MODP(tau - 3, SLOTS) * PLANEF;
            float cx0 = pc[nb0 + RS + 1];
            float cx1 = pc[nb0 + RS + 2];
            float2 o = make_float2(cx0 * g0, cx1 * g1);
            *(float2*)(op + (size_t)tout * HW + obase) = o;
        }
    };

    // Prologue: stage planes 0,1,2 as one cp.async group
    stage(0); stage(1); stage(2); CP_COMMIT;

    #pragma unroll
    for (int q = 0; q < 12; ++q) {
        const int tA = 3 * q;

        if (tA < T_) {
            // Stage next triple (overlaps with this round's compute)
            #pragma unroll
            for (int j = 0; j < 3; ++j)
                if (tA + 3 + j < T_) stage(tA + 3 + j);
            CP_COMMIT;
            CP_WAIT1;             // previous triple resident
            __syncthreads();

            // Fused triple conv: each weight load feeds up to 3 planes
            #pragma unroll
            for (int dy = 0; dy < 3; ++dy) {
                ull a01[3], a23[3], am[3];
                #pragma unroll
                for (int j = 0; j < 3; ++j) {
                    if (tA + j < T_) {
                        const float* rp = plane0
                            + MODP(tA + j, SLOTS) * PLANEF + nb0 + dy * RS;
                        a01[j] = *(const ull*)(rp);
                        a23[j] = *(const ull*)(rp + 2);
                        MIDP(am[j], a01[j], a23[j]);
                    }
                }
                #pragma unroll
                for (int sl = 0; sl < 9; ++sl) {
                    const ulonglong2 wv = *(const ulonglong2*)(&wdup[sl][dy][0]);
                    const ull w2v = wdup[sl][dy][2];
                    #pragma unroll
                    for (int j = 0; j < 3; ++j) {
                        if (tA + j < T_) {
                            ull& q_ = aref(sl, tA + j);
                            if ((sl % 3) == 0 && dy == 0) {
                                MUL2(q_, wv.x, a01[j]);
                                FMA2(q_, wv.y, am[j]);
                                FMA2(q_, w2v, a23[j]);
                            } else {
                                FMA2(q_, wv.x, a01[j]);
                                FMA2(q_, wv.y, am[j]);
                                FMA2(q_, w2v, a23[j]);
                            }
                        }
                    }
                }
            }
        }

        #pragma unroll
        for (int j = 0; j < 3; ++j)
            if (tA + j <= T_ + 2) completion(tA + j);
    }
}

extern "C" void kernel_launch(void* const* d_in, const int* in_sizes, int n_in,
                              void* d_out, int out_size) {
    const float* x  = (const float*)d_in[0];
    const float* w1 = (const float*)d_in[1];
    const float* b1 = (const float*)d_in[2];
    const float* w2 = (const float*)d_in[3];
    const float* b2 = (const float*)d_in[4];
    const float* w3 = (const float*)d_in[5];
    const float* b3 = (const float*)d_in[6];
    const float* wg = (const float*)d_in[7];
    float* out = (float*)d_out;

    // ~45.8 KB static smem/CTA; max shared carveout so 3 CTAs/SM fit
    // comfortably. Host-side, outside graph capture, deterministic.
    static int carveout_set = 0;
    if (!carveout_set) {
        cudaFuncSetAttribute(tts_kernel,
                             cudaFuncAttributePreferredSharedMemoryCarveout,
                             100);
        carveout_set = 1;
    }

    dim3 grid(B_ * C_ * NTILES);   // 1792
    dim3 block(NT);                // 224
    tts_kernel<<<grid, block>>>(x, w1, b1, w2, b2, w3, b3, wg, out);
}